// round 1
// baseline (speedup 1.0000x reference)
#include <cuda_runtime.h>
#include <cstdint>
#include <cmath>

// Problem dims (fixed)
#define B_ 4
#define L_ 2048
#define D_ 2048
#define M_ (B_*L_)          // 8192 tokens
#define NSEG 16
#define SEGLEN (L_/NSEG)    // 128

// ------------------------- scratch (static device globals) -------------------------
__device__ __align__(16) int8_t g_xq[(size_t)M_*D_];       // 16 MB
__device__ float  g_xsc[M_];                                // per-token dequant a_t
__device__ __align__(16) int8_t g_wq[4][(size_t)D_*D_];     // 16 MB ternary weights
__device__ float  g_wpart[4][2048];
__device__ float  g_wscale[4];                              // b_w = clip(mean|w|,1e-5)
__device__ float  g_ilin[(size_t)M_*D_];                    // 64 MB
__device__ float  g_flin[(size_t)M_*D_];                    // 64 MB
__device__ float  g_glin[(size_t)M_*D_];                    // 64 MB
__device__ float  g_ov  [(size_t)M_*D_];                    // 64 MB scan output o
__device__ __align__(16) int8_t g_yq[(size_t)M_*D_];        // 16 MB
__device__ float  g_ysc[M_];
__device__ float  g_segP[NSEG][B_*D_];
__device__ float  g_segH[NSEG][B_*D_];
__device__ float  g_carry[NSEG][B_*D_];

// ------------------------- helpers -------------------------
__device__ __forceinline__ float block_reduce_sum(float v, float* red) {
    int tid = threadIdx.x;
    red[tid] = v; __syncthreads();
    #pragma unroll
    for (int s = 128; s > 0; s >>= 1) {
        if (tid < s) red[tid] += red[tid + s];
        __syncthreads();
    }
    float r = red[0]; __syncthreads();
    return r;
}

__device__ __forceinline__ float block_reduce_max(float v, float* red) {
    int tid = threadIdx.x;
    red[tid] = v; __syncthreads();
    #pragma unroll
    for (int s = 128; s > 0; s >>= 1) {
        if (tid < s) red[tid] = fmaxf(red[tid], red[tid + s]);
        __syncthreads();
    }
    float r = red[0]; __syncthreads();
    return r;
}

__device__ __forceinline__ float sigmoidf_(float x) { return 1.f / (1.f + expf(-x)); }

// ------------------------- 1) activation quant -------------------------
__global__ void quant_x_kernel(const float* __restrict__ x) {
    __shared__ float red[256];
    int t = blockIdx.x;
    const float* row = x + (size_t)t * D_;
    float v[8];
    float amax = 0.f;
    #pragma unroll
    for (int k = 0; k < 8; k++) {
        v[k] = row[threadIdx.x + k * 256];
        amax = fmaxf(amax, fabsf(v[k]));
    }
    amax = block_reduce_max(amax, red);
    amax = fmaxf(amax, 1e-5f);
    float s = 127.f / amax;
    if (threadIdx.x == 0) g_xsc[t] = amax / 127.f;
    int8_t* q = g_xq + (size_t)t * D_;
    #pragma unroll
    for (int k = 0; k < 8; k++) {
        float r = rintf(v[k] * s);
        r = fminf(fmaxf(r, -128.f), 127.f);
        q[threadIdx.x + k * 256] = (int8_t)r;
    }
}

// ------------------------- 2) weight quant (deterministic tree reduce) -------------------------
__global__ void wabs_partial_kernel(const float* __restrict__ w0, const float* __restrict__ w1,
                                    const float* __restrict__ w2, const float* __restrict__ w3) {
    __shared__ float red[256];
    const float* w = (blockIdx.y == 0) ? w0 : (blockIdx.y == 1) ? w1 : (blockIdx.y == 2) ? w2 : w3;
    size_t base = (size_t)blockIdx.x * 2048 + threadIdx.x;
    float s = 0.f;
    #pragma unroll
    for (int k = 0; k < 8; k++) s += fabsf(w[base + k * 256]);
    float tot = block_reduce_sum(s, red);
    if (threadIdx.x == 0) g_wpart[blockIdx.y][blockIdx.x] = tot;
}

__global__ void wabs_final_kernel() {
    __shared__ float red[256];
    int t = blockIdx.x;
    float s = 0.f;
    #pragma unroll
    for (int k = 0; k < 8; k++) s += g_wpart[t][threadIdx.x + k * 256];
    float tot = block_reduce_sum(s, red);
    if (threadIdx.x == 0)
        g_wscale[t] = fmaxf(tot / ((float)D_ * (float)D_), 1e-5f);
}

__global__ void wquant_kernel(const float* __restrict__ w0, const float* __restrict__ w1,
                              const float* __restrict__ w2, const float* __restrict__ w3) {
    const float* w = (blockIdx.y == 0) ? w0 : (blockIdx.y == 1) ? w1 : (blockIdx.y == 2) ? w2 : w3;
    float s = 1.f / g_wscale[blockIdx.y];
    size_t base = (size_t)blockIdx.x * 2048 + threadIdx.x;
    int8_t* q = g_wq[blockIdx.y];
    #pragma unroll
    for (int k = 0; k < 8; k++) {
        float r = rintf(w[base + k * 256] * s);
        r = fminf(fmaxf(r, -1.f), 1.f);
        q[base + k * 256] = (int8_t)r;
    }
}

// ------------------------- 3) int8 GEMM: C[m,n] = (sum_k A[m,k]*W[n,k]) * a[m]*b -------------------------
// Block tile 128x128, K-chunk 64, 8 warps (2x4), warp tile 64x32, mma m16n8k32 s8s8s32.
#define BM 128
#define BN 128
#define BK 64
#define SROW 80   // smem row stride in bytes (64 data + 16 pad => conflict-free ldmatrix)

__device__ __forceinline__ void cp16(void* smem, const void* gmem) {
    uint32_t d = (uint32_t)__cvta_generic_to_shared(smem);
    asm volatile("cp.async.cg.shared.global [%0], [%1], 16;\n" :: "r"(d), "l"(gmem));
}
__device__ __forceinline__ void ldsm_x4(uint32_t& r0, uint32_t& r1, uint32_t& r2, uint32_t& r3, uint32_t addr) {
    asm volatile("ldmatrix.sync.aligned.m8n8.x4.shared.b16 {%0,%1,%2,%3}, [%4];\n"
                 : "=r"(r0), "=r"(r1), "=r"(r2), "=r"(r3) : "r"(addr));
}

__global__ __launch_bounds__(256) void gemm_s8_kernel(int which, float* __restrict__ final_out) {
    __shared__ __align__(16) int8_t sA[2][BM * SROW];
    __shared__ __align__(16) int8_t sB[2][BN * SROW];

    const int8_t* __restrict__ Aq  = (which == 3) ? g_yq : g_xq;
    const float*  __restrict__ asc = (which == 3) ? g_ysc : g_xsc;
    const int8_t* __restrict__ Wq  = g_wq[which];
    float* __restrict__ C = final_out;
    if (which == 0) C = g_ilin; else if (which == 1) C = g_flin; else if (which == 2) C = g_glin;
    const float bscale = g_wscale[which];

    const int tid = threadIdx.x;
    const int warp = tid >> 5, lane = tid & 31;
    const int wm = (warp >> 2) * 64;   // 0 or 64
    const int wn = (warp & 3) * 32;    // 0..96
    const int bm = blockIdx.y * BM;
    const int bn = blockIdx.x * BN;

    int acc[4][4][4];
    #pragma unroll
    for (int mi = 0; mi < 4; mi++)
        #pragma unroll
        for (int nj = 0; nj < 4; nj++)
            #pragma unroll
            for (int c = 0; c < 4; c++) acc[mi][nj][c] = 0;

    auto load_tile = [&](int kt, int buf) {
        int k0 = kt * BK;
        #pragma unroll
        for (int i = 0; i < 2; i++) {
            int id = tid + i * 256;
            int r = id >> 2, cs = (id & 3) * 16;
            cp16(&sA[buf][r * SROW + cs], Aq + (size_t)(bm + r) * D_ + k0 + cs);
        }
        #pragma unroll
        for (int i = 0; i < 2; i++) {
            int id = tid + i * 256;
            int r = id >> 2, cs = (id & 3) * 16;
            cp16(&sB[buf][r * SROW + cs], Wq + (size_t)(bn + r) * D_ + k0 + cs);
        }
        asm volatile("cp.async.commit_group;\n");
    };

    load_tile(0, 0);
    const int KT = D_ / BK;   // 32
    for (int kt = 0; kt < KT; kt++) {
        int buf = kt & 1;
        asm volatile("cp.async.wait_group 0;\n" ::: "memory");
        __syncthreads();
        if (kt + 1 < KT) load_tile(kt + 1, buf ^ 1);

        #pragma unroll
        for (int ks = 0; ks < 2; ks++) {
            int kb = ks * 32;
            int rsel = (lane & 7) + ((lane >> 3) & 1) * 8;
            int csel = kb + (lane >> 4) * 16;

            uint32_t af[4][4];
            #pragma unroll
            for (int mi = 0; mi < 4; mi++) {
                int row = wm + mi * 16 + rsel;
                uint32_t addr = (uint32_t)__cvta_generic_to_shared(&sA[buf][row * SROW + csel]);
                ldsm_x4(af[mi][0], af[mi][1], af[mi][2], af[mi][3], addr);
            }
            uint32_t bf[4][2];
            #pragma unroll
            for (int np = 0; np < 2; np++) {
                int row = wn + np * 16 + rsel;
                uint32_t addr = (uint32_t)__cvta_generic_to_shared(&sB[buf][row * SROW + csel]);
                uint32_t t0, t1, t2, t3;
                ldsm_x4(t0, t1, t2, t3, addr);
                bf[np * 2 + 0][0] = t0; bf[np * 2 + 0][1] = t2;
                bf[np * 2 + 1][0] = t1; bf[np * 2 + 1][1] = t3;
            }
            #pragma unroll
            for (int mi = 0; mi < 4; mi++)
                #pragma unroll
                for (int nj = 0; nj < 4; nj++) {
                    asm volatile(
                        "mma.sync.aligned.m16n8k32.row.col.s32.s8.s8.s32 "
                        "{%0,%1,%2,%3}, {%4,%5,%6,%7}, {%8,%9}, {%0,%1,%2,%3};\n"
                        : "+r"(acc[mi][nj][0]), "+r"(acc[mi][nj][1]),
                          "+r"(acc[mi][nj][2]), "+r"(acc[mi][nj][3])
                        : "r"(af[mi][0]), "r"(af[mi][1]), "r"(af[mi][2]), "r"(af[mi][3]),
                          "r"(bf[nj][0]), "r"(bf[nj][1]));
                }
        }
        __syncthreads();
    }

    // epilogue: dequant + store
    #pragma unroll
    for (int mi = 0; mi < 4; mi++) {
        int r0 = bm + wm + mi * 16 + (lane >> 2);
        int r1 = r0 + 8;
        float s0 = asc[r0] * bscale;
        float s1 = asc[r1] * bscale;
        #pragma unroll
        for (int nj = 0; nj < 4; nj++) {
            int col = bn + wn + nj * 8 + (lane & 3) * 2;
            float2 v0 = make_float2((float)acc[mi][nj][0] * s0, (float)acc[mi][nj][1] * s0);
            float2 v1 = make_float2((float)acc[mi][nj][2] * s1, (float)acc[mi][nj][3] * s1);
            *(float2*)&C[(size_t)r0 * D_ + col] = v0;
            *(float2*)&C[(size_t)r1 * D_ + col] = v1;
        }
    }
}

// ------------------------- 4) segmented HGRN scan (gating fused) -------------------------
__global__ void scan_pass1_kernel() {
    int d = blockIdx.x * 256 + threadIdx.x;
    int b = blockIdx.y;
    int s = blockIdx.z;
    size_t base = ((size_t)(b * L_ + s * SEGLEN)) * D_ + d;
    float h = 0.f, P = 1.f;
    #pragma unroll 4
    for (int l = 0; l < SEGLEN; l++) {
        float fr = g_flin[base];
        float ir = g_ilin[base];
        float f = sigmoidf_(fr);
        float z = 1.f - f;
        float ig = ir * z * sigmoidf_(z);   // i * silu(1-f)
        h = fmaf(f, h, ig);
        P *= f;
        base += D_;
    }
    int ch = b * D_ + d;
    g_segP[s][ch] = P;
    g_segH[s][ch] = h;
}

__global__ void scan_carry_kernel() {
    int ch = blockIdx.x * 256 + threadIdx.x;
    float c = 0.f;
    #pragma unroll
    for (int s = 0; s < NSEG; s++) {
        g_carry[s][ch] = c;
        c = fmaf(g_segP[s][ch], c, g_segH[s][ch]);
    }
}

__global__ void scan_pass2_kernel() {
    int d = blockIdx.x * 256 + threadIdx.x;
    int b = blockIdx.y;
    int s = blockIdx.z;
    int ch = b * D_ + d;
    size_t base = ((size_t)(b * L_ + s * SEGLEN)) * D_ + d;
    float h = g_carry[s][ch];
    #pragma unroll 4
    for (int l = 0; l < SEGLEN; l++) {
        float fr = g_flin[base];
        float ir = g_ilin[base];
        float f = sigmoidf_(fr);
        float z = 1.f - f;
        float ig = ir * z * sigmoidf_(z);
        h = fmaf(f, h, ig);
        g_ov[base] = h;
        base += D_;
    }
}

// ------------------------- 5) RMSNorm + swish gate + re-quant y -------------------------
__global__ void gate_kernel(const float* __restrict__ gnw) {
    __shared__ float red[256];
    int t = blockIdx.x;
    size_t base = (size_t)t * D_;
    float gv[8];
    float ss = 0.f;
    #pragma unroll
    for (int k = 0; k < 8; k++) {
        gv[k] = g_glin[base + threadIdx.x + k * 256];
        ss += gv[k] * gv[k];
    }
    float tot = block_reduce_sum(ss, red);
    float rms = rsqrtf(tot / (float)D_ + 1e-5f);

    float amax = 0.f;
    #pragma unroll
    for (int k = 0; k < 8; k++) {
        int d = threadIdx.x + k * 256;
        float ov = g_ov[base + d];
        float y = gv[k] * rms * gnw[d] * ov * sigmoidf_(ov);
        gv[k] = y;
        amax = fmaxf(amax, fabsf(y));
    }
    amax = block_reduce_max(amax, red);
    amax = fmaxf(amax, 1e-5f);
    float s = 127.f / amax;
    if (threadIdx.x == 0) g_ysc[t] = amax / 127.f;
    #pragma unroll
    for (int k = 0; k < 8; k++) {
        float r = rintf(gv[k] * s);
        r = fminf(fmaxf(r, -128.f), 127.f);
        g_yq[base + threadIdx.x + k * 256] = (int8_t)r;
    }
}

// ------------------------- launch -------------------------
extern "C" void kernel_launch(void* const* d_in, const int* in_sizes, int n_in,
                              void* d_out, int out_size) {
    const float* x   = (const float*)d_in[0];
    const float* wi  = (const float*)d_in[1];
    const float* wf  = (const float*)d_in[2];
    const float* wg  = (const float*)d_in[3];
    const float* wo  = (const float*)d_in[4];
    const float* gnw = (const float*)d_in[5];
    float* out = (float*)d_out;

    quant_x_kernel<<<M_, 256>>>(x);
    wabs_partial_kernel<<<dim3(2048, 4), 256>>>(wi, wf, wg, wo);
    wabs_final_kernel<<<4, 256>>>();
    wquant_kernel<<<dim3(2048, 4), 256>>>(wi, wf, wg, wo);

    dim3 ggrid(D_ / BN, M_ / BM);   // (16, 64)
    gemm_s8_kernel<<<ggrid, 256>>>(0, nullptr);  // i_lin
    gemm_s8_kernel<<<ggrid, 256>>>(1, nullptr);  // f_lin
    gemm_s8_kernel<<<ggrid, 256>>>(2, nullptr);  // g_lin

    scan_pass1_kernel<<<dim3(D_ / 256, B_, NSEG), 256>>>();
    scan_carry_kernel<<<(B_ * D_) / 256, 256>>>();
    scan_pass2_kernel<<<dim3(D_ / 256, B_, NSEG), 256>>>();

    gate_kernel<<<M_, 256>>>(gnw);

    gemm_s8_kernel<<<ggrid, 256>>>(3, out);      // final projection
}